// round 1
// baseline (speedup 1.0000x reference)
#include <cuda_runtime.h>

#define N 192
#define TX 32
#define TY 8
#define NT (TX*TY)
#define ZCHUNK 48
#define PW (TX+4)   // 36
#define PH (TY+4)   // 12

__device__ __forceinline__ void load_plane(float* dst, const float* __restrict__ imgb,
                                           int zp, int bx0, int by0, int tid) {
    const float* src = imgb + (size_t)zp * (N * N);
    const bool zok = (zp >= 0) && (zp < N);
    for (int i = tid; i < PH * PW; i += NT) {
        int px = i % PW;
        int py = i / PW;
        int gx = bx0 + px - 2;
        int gy = by0 + py - 2;
        float v = 0.f;
        if (zok && gx >= 0 && gx < N && gy >= 0 && gy < N)
            v = src[gy * N + gx];
        dst[i] = v;
    }
}

__global__ void __launch_bounds__(NT, 4)
mind_kernel(const float* __restrict__ img, float* __restrict__ out, int nchunk) {
    __shared__ float s_img[3][PH * PW];
    __shared__ float s_cx[6][TY + 2][TX];

    const int lx  = threadIdx.x;
    const int ly  = threadIdx.y;
    const int tid = ly * TX + lx;
    const int bx0 = blockIdx.x * TX;
    const int by0 = blockIdx.y * TY;
    const int b   = blockIdx.z / nchunk;
    const int z0  = (blockIdx.z % nchunk) * ZCHUNK;

    const float A    = 0.018315639f;                  // exp(-4) : 1D Gaussian tap
    const float NORM = 1.0f / ((1.f + 2.f * A) * (1.f + 2.f * A) * (1.f + 2.f * A));
    const float EPS  = 1e-8f;

    const size_t vol = (size_t)N * N * N;
    const float* imgb = img + (size_t)b * vol;
    float* outb = out + (size_t)b * 6 * vol;

    // preload planes z0-2, z0-1 into ring slots 0,1
    load_plane(s_img[0], imgb, z0 - 2, bx0, by0, tid);
    load_plane(s_img[1], imgb, z0 - 1, bx0, by0, tid);

    // register ring of 2D-convolved diff2 planes S(z): S0=S(zs-2), S1=S(zs-1), S2=S(zs)
    float S0[6], S1[6], S2[6];
#pragma unroll
    for (int c = 0; c < 6; c++) { S0[c] = 0.f; S1[c] = 0.f; S2[c] = 0.f; }

    for (int t = 0; t <= ZCHUNK + 1; ++t) {
        const int zs = z0 - 1 + t;      // plane whose S we compute this step

        __syncthreads();                                   // A: prior reads of ring slot done
        load_plane(s_img[(t + 2) % 3], imgb, zs + 1, bx0, by0, tid);
        __syncthreads();                                   // B: img plane ready

        const bool zvalid = (zs >= 0) && (zs < N);
        if (zvalid) {
            const float* Pm = s_img[t % 3];        // plane zs-1
            const float* P0 = s_img[(t + 1) % 3];  // plane zs
            const float* Pp = s_img[(t + 2) % 3];  // plane zs+1
            // compute x-convolved diff2 rows cx for y' in [-1, TY+1)
            for (int i = tid; i < TX * (TY + 2); i += NT) {
                const int px = i & (TX - 1);
                const int py = i >> 5;             // 0..TY+1, y' = py-1
                const int gy = by0 + py - 1;
                float cx0 = 0.f, cx1 = 0.f, cx2 = 0.f, cx3 = 0.f, cx4 = 0.f, cx5 = 0.f;
                if (gy >= 0 && gy < N) {
                    const int gx = bx0 + px;
                    const int rb = (py + 1) * PW + px;     // row py+1, col = dx=-2
                    const float c5a[5] = { P0[rb + 0], P0[rb + 1], P0[rb + 2],
                                           P0[rb + 3], P0[rb + 4] };
                    // tap weight masked: diff2 at OOB x-center is exactly zero
                    const float wv[3] = { (gx >= 1) ? A : 0.f, 1.f, (gx < N - 1) ? A : 0.f };
#pragma unroll
                    for (int j = 0; j < 3; ++j) {
                        const float ce = c5a[j + 1];
                        const float w  = wv[j];
                        float d;
                        d = Pp[rb + 1 + j]      - ce;  cx0 = fmaf(d * d, w, cx0);  // +z
                        d = Pm[rb + 1 + j]      - ce;  cx1 = fmaf(d * d, w, cx1);  // -z
                        d = P0[rb + PW + 1 + j] - ce;  cx2 = fmaf(d * d, w, cx2);  // +y
                        d = P0[rb - PW + 1 + j] - ce;  cx3 = fmaf(d * d, w, cx3);  // -y
                        d = c5a[j + 2]          - ce;  cx4 = fmaf(d * d, w, cx4);  // +x
                        d = c5a[j]              - ce;  cx5 = fmaf(d * d, w, cx5);  // -x
                    }
                }
                s_cx[0][py][px] = cx0; s_cx[1][py][px] = cx1; s_cx[2][py][px] = cx2;
                s_cx[3][py][px] = cx3; s_cx[4][py][px] = cx4; s_cx[5][py][px] = cx5;
            }
        }
        __syncthreads();                                   // C: cx ready

        // shift the z register ring
#pragma unroll
        for (int c = 0; c < 6; c++) { S0[c] = S1[c]; S1[c] = S2[c]; }
        if (zvalid) {
#pragma unroll
            for (int c = 0; c < 6; c++)
                S2[c] = fmaf(A, s_cx[c][ly][lx] + s_cx[c][ly + 2][lx], s_cx[c][ly + 1][lx]);
        } else {
#pragma unroll
            for (int c = 0; c < 6; c++) S2[c] = 0.f;       // zero-padded diff2 plane
        }

        // output plane zo = zs-1 once ring is primed
        if (t >= 2) {
            const int zo = zs - 1;
            float Dp[6];
            float sd = 0.f;
#pragma unroll
            for (int c = 0; c < 6; c++) {
                Dp[c] = NORM * fmaf(A, S0[c] + S2[c], S1[c]);
                sd += Dp[c];
            }
            const float inv = __fdividef(1.f, sd * (1.f / 6.f) + EPS);
            float num[6];
            float s = 0.f;
#pragma unroll
            for (int c = 0; c < 6; c++) { num[c] = __expf(-Dp[c] * inv); s += num[c]; }
            const float invs = __fdividef(1.f, s + EPS);
            const size_t base = ((size_t)zo * N + (by0 + ly)) * N + (bx0 + lx);
#pragma unroll
            for (int c = 0; c < 6; c++)
                outb[(size_t)c * vol + base] = num[c] * invs;
        }
    }
}

extern "C" void kernel_launch(void* const* d_in, const int* in_sizes, int n_in,
                              void* d_out, int out_size) {
    const float* img = (const float*)d_in[0];
    float* out = (float*)d_out;
    const int B = in_sizes[0] / (N * N * N);
    const int nchunk = N / ZCHUNK;
    dim3 block(TX, TY, 1);
    dim3 grid(N / TX, N / TY, B * nchunk);
    mind_kernel<<<grid, block>>>(img, out, nchunk);
}

// round 2
// speedup vs baseline: 1.1479x; 1.1479x over previous
#include <cuda_runtime.h>

#define N 192
#define TX 32
#define TY 8
#define NT 256
#define ZCHUNK 48
#define NCHUNK 4          // N / ZCHUNK, compile-time
#define PW 36             // TX + 4
#define PH 12             // TY + 4
#define PLANE (PH*PW)     // 432
#define VOL ((size_t)N*(size_t)N*(size_t)N)

__global__ void __launch_bounds__(NT, 4)
mind_kernel(const float* __restrict__ img, float* __restrict__ out) {
    __shared__ float s_img[3][PLANE];
    __shared__ float s_cx[6][TY + 2][TX];

    const int lx  = threadIdx.x;
    const int ly  = threadIdx.y;
    const int tid = ly * TX + lx;
    const int bx0 = blockIdx.x * TX;
    const int by0 = blockIdx.y * TY;
    const int b   = blockIdx.z >> 2;                 // NCHUNK == 4
    const int z0  = (blockIdx.z & (NCHUNK - 1)) * ZCHUNK;

    constexpr float A    = 0.018315639f;             // exp(-4): 1D Gaussian side tap
    constexpr float NORM = 1.0f / ((1.f + 2.f * A) * (1.f + 2.f * A) * (1.f + 2.f * A));
    constexpr float EPS  = 1e-8f;

    const float* imgb = img + (size_t)b * VOL;
    float* outb = out + (size_t)b * 6 * VOL;

    // ---- hoisted halo-load geometry (iteration-invariant) ----
    int h1_off, h1_ok;
    {
        const int px = tid % PW, py = tid / PW;
        const int gxh = bx0 + px - 2, gyh = by0 + py - 2;
        h1_ok  = ((unsigned)gxh < (unsigned)N) & ((unsigned)gyh < (unsigned)N);
        h1_off = gyh * N + gxh;
    }
    int h2_off = 0, h2_ok = 0;
    {
        const int i = tid + NT;
        if (i < PLANE) {
            const int px = i % PW, py = i / PW;
            const int gxh = bx0 + px - 2, gyh = by0 + py - 2;
            h2_ok  = ((unsigned)gxh < (unsigned)N) & ((unsigned)gyh < (unsigned)N);
            h2_off = gyh * N + gxh;
        }
    }

    auto load_plane = [&](float* dst, int zp) {
        const int zok = (unsigned)zp < (unsigned)N;
        const float* src = imgb + (size_t)zp * (N * N);
        float v1 = 0.f;
        if (zok & h1_ok) v1 = __ldg(src + h1_off);
        dst[tid] = v1;
        if (tid < PLANE - NT) {
            float v2 = 0.f;
            if (zok & h2_ok) v2 = __ldg(src + h2_off);
            dst[tid + NT] = v2;
        }
    };

    // ---- hoisted stage-2 geometry ----
    const int   gx = bx0 + lx;
    const float wl = (gx >= 1)     ? A : 0.f;        // Gaussian x-tap masks at volume border
    const float wr = (gx <= N - 2) ? A : 0.f;

    const int  rbA = (ly + 1) * PW + lx;             // posA: y' = ly-1
    const int  cyA = ly;
    const int  yvA = (by0 + ly - 1) >= 0;            // upper bound always satisfied
    const int  rbB = (9 + ly) * PW + lx;             // posB: y' = 7+ly (warps ly<2 only)
    const int  cyB = 8 + ly;
    const int  yvB = (by0 + 7 + ly) < N;
    const bool hasB = (ly < 2);

    auto stage2 = [&](const float* Pm, const float* P0, const float* Pp,
                      int rb, int cy, int yv) {
        float c0 = 0.f, c1 = 0.f, c2 = 0.f, c3 = 0.f, c4 = 0.f, c5 = 0.f;
        if (yv) {
            const float a0 = P0[rb],     a1 = P0[rb + 1], a2 = P0[rb + 2];
            const float a3 = P0[rb + 3], a4 = P0[rb + 4];
            const float m0 = Pm[rb + 1], m1 = Pm[rb + 2], m2 = Pm[rb + 3];
            const float p0 = Pp[rb + 1], p1 = Pp[rb + 2], p2 = Pp[rb + 3];
            const float u0 = P0[rb + PW + 1], u1 = P0[rb + PW + 2], u2 = P0[rb + PW + 3];
            const float e0 = P0[rb - PW + 1], e1 = P0[rb - PW + 2], e2 = P0[rb - PW + 3];
            float d;
            // j=0: center a1, weight wl
            d = p0 - a1; c0 = d * d * wl;
            d = m0 - a1; c1 = d * d * wl;
            d = u0 - a1; c2 = d * d * wl;
            d = e0 - a1; c3 = d * d * wl;
            d = a2 - a1; c4 = d * d * wl;
            d = a0 - a1; c5 = d * d * wl;
            // j=1: center a2, weight 1
            d = p1 - a2; c0 = fmaf(d, d, c0);
            d = m1 - a2; c1 = fmaf(d, d, c1);
            d = u1 - a2; c2 = fmaf(d, d, c2);
            d = e1 - a2; c3 = fmaf(d, d, c3);
            d = a3 - a2; c4 = fmaf(d, d, c4);
            d = a1 - a2; c5 = fmaf(d, d, c5);
            // j=2: center a3, weight wr
            d = p2 - a3; c0 = fmaf(d * d, wr, c0);
            d = m2 - a3; c1 = fmaf(d * d, wr, c1);
            d = u2 - a3; c2 = fmaf(d * d, wr, c2);
            d = e2 - a3; c3 = fmaf(d * d, wr, c3);
            d = a4 - a3; c4 = fmaf(d * d, wr, c4);
            d = a2 - a3; c5 = fmaf(d * d, wr, c5);
        }
        s_cx[0][cy][lx] = c0; s_cx[1][cy][lx] = c1; s_cx[2][cy][lx] = c2;
        s_cx[3][cy][lx] = c3; s_cx[4][cy][lx] = c4; s_cx[5][cy][lx] = c5;
    };

    // preload planes z0-2, z0-1
    load_plane(s_img[0], z0 - 2);
    load_plane(s_img[1], z0 - 1);

    float S0[6], S1[6], S2[6];
#pragma unroll
    for (int c = 0; c < 6; c++) { S0[c] = 0.f; S1[c] = 0.f; S2[c] = 0.f; }

    float* r0 = s_img[0];
    float* r1 = s_img[1];
    float* r2 = s_img[2];

#pragma unroll 3
    for (int t = 0; t <= ZCHUNK + 1; ++t) {
        const int zs = z0 - 1 + t;                   // plane whose 2D-smoothed diff2 we build
        load_plane(r2, zs + 1);
        __syncthreads();                             // img plane ready; prior s_cx reads done

        const int zvalid = (unsigned)zs < (unsigned)N;
        if (zvalid) {
            stage2(r0, r1, r2, rbA, cyA, yvA);
            if (hasB) stage2(r0, r1, r2, rbB, cyB, yvB);
        }
        __syncthreads();                             // s_cx ready

#pragma unroll
        for (int c = 0; c < 6; c++) { S0[c] = S1[c]; S1[c] = S2[c]; }
        if (zvalid) {
#pragma unroll
            for (int c = 0; c < 6; c++)
                S2[c] = fmaf(A, s_cx[c][ly][lx] + s_cx[c][ly + 2][lx], s_cx[c][ly + 1][lx]);
        } else {
#pragma unroll
            for (int c = 0; c < 6; c++) S2[c] = 0.f;
        }

        if (t >= 2) {
            const int zo = zs - 1;
            float Dp[6];
            float sd = 0.f;
#pragma unroll
            for (int c = 0; c < 6; c++) {
                Dp[c] = NORM * fmaf(A, S0[c] + S2[c], S1[c]);
                sd += Dp[c];
            }
            const float inv = __fdividef(6.f, fmaf(6.f, EPS, sd));  // 1/(sd/6 + EPS)
            float num[6];
            float s = 0.f;
#pragma unroll
            for (int c = 0; c < 6; c++) { num[c] = __expf(-Dp[c] * inv); s += num[c]; }
            const float invs = __fdividef(1.f, s + EPS);
            const size_t base = ((size_t)zo * N + (by0 + ly)) * N + gx;
#pragma unroll
            for (int c = 0; c < 6; c++)
                outb[(size_t)c * VOL + base] = num[c] * invs;
        }

        float* tmp = r0; r0 = r1; r1 = r2; r2 = tmp;  // ring rotate (renamed under unroll)
    }
}

extern "C" void kernel_launch(void* const* d_in, const int* in_sizes, int n_in,
                              void* d_out, int out_size) {
    const float* img = (const float*)d_in[0];
    float* out = (float*)d_out;
    const int B = in_sizes[0] / (int)(N * N * N);
    dim3 block(TX, TY, 1);
    dim3 grid(N / TX, N / TY, B * NCHUNK);
    mind_kernel<<<grid, block>>>(img, out);
}

// round 3
// speedup vs baseline: 1.4594x; 1.2713x over previous
#include <cuda_runtime.h>

#define N 192
#define TX 32
#define TY 8
#define NT 256
#define ZCHUNK 48
#define NCHUNK 4          // N / ZCHUNK, compile-time
#define PW 36             // TX + 4
#define PH 12             // TY + 4
#define PLANE (PH*PW)     // 432
#define VOL ((size_t)N*(size_t)N*(size_t)N)

__global__ void __launch_bounds__(NT, 4)
mind_kernel(const float* __restrict__ img, float* __restrict__ out) {
    __shared__ float s_img[3][PLANE];
    __shared__ float s_cx[6][TY + 2][TX];

    const int lx  = threadIdx.x;
    const int ly  = threadIdx.y;
    const int tid = ly * TX + lx;
    const int bx0 = blockIdx.x * TX;
    const int by0 = blockIdx.y * TY;
    const int b   = blockIdx.z >> 2;                 // NCHUNK == 4
    const int z0  = (blockIdx.z & (NCHUNK - 1)) * ZCHUNK;

    constexpr float A    = 0.018315639f;             // exp(-4): 1D Gaussian side tap
    constexpr float NORM = 1.0f / ((1.f + 2.f * A) * (1.f + 2.f * A) * (1.f + 2.f * A));
    constexpr float EPS  = 1e-8f;

    const float* imgb = img + (size_t)b * VOL;
    float* outb = out + (size_t)b * 6 * VOL;

    // ---- hoisted halo-load geometry (iteration-invariant) ----
    int h1_off, h1_ok;
    {
        const int px = tid % PW, py = tid / PW;
        const int gxh = bx0 + px - 2, gyh = by0 + py - 2;
        h1_ok  = ((unsigned)gxh < (unsigned)N) & ((unsigned)gyh < (unsigned)N);
        h1_off = gyh * N + gxh;
    }
    int h2_off = 0, h2_ok = 0;
    const bool has2 = (tid < PLANE - NT);
    {
        const int i = tid + NT;
        if (i < PLANE) {
            const int px = i % PW, py = i / PW;
            const int gxh = bx0 + px - 2, gyh = by0 + py - 2;
            h2_ok  = ((unsigned)gxh < (unsigned)N) & ((unsigned)gyh < (unsigned)N);
            h2_off = gyh * N + gxh;
        }
    }

    // issue global loads for plane zp into registers (latency overlapped by caller)
    auto prefetch = [&](int zp, float& v1, float& v2) {
        const int zok = (unsigned)zp < (unsigned)N;
        const float* src = imgb + (size_t)zp * (N * N);
        v1 = 0.f; v2 = 0.f;
        if (zok & h1_ok) v1 = __ldg(src + h1_off);
        if (has2 && (zok & h2_ok)) v2 = __ldg(src + h2_off);
    };
    auto commit = [&](float* dst, float v1, float v2) {
        dst[tid] = v1;
        if (has2) dst[tid + NT] = v2;
    };

    // ---- hoisted stage-2 geometry ----
    const int   gx = bx0 + lx;
    const float wl = (gx >= 1)     ? A : 0.f;        // Gaussian x-tap masks at volume border
    const float wr = (gx <= N - 2) ? A : 0.f;

    const int  rbA = (ly + 1) * PW + lx;             // posA: y' = ly-1
    const int  cyA = ly;
    const int  yvA = (by0 + ly - 1) >= 0;
    const int  rbB = (9 + ly) * PW + lx;             // posB: y' = 7+ly (ly<2 only)
    const int  cyB = 8 + ly;
    const int  yvB = (by0 + 7 + ly) < N;
    const bool hasB = (ly < 2);

    auto stage2 = [&](const float* Pm, const float* P0, const float* Pp,
                      int rb, int cy, int yv) {
        float c0 = 0.f, c1 = 0.f, c2 = 0.f, c3 = 0.f, c4 = 0.f, c5 = 0.f;
        if (yv) {
            const float a0 = P0[rb],     a1 = P0[rb + 1], a2 = P0[rb + 2];
            const float a3 = P0[rb + 3], a4 = P0[rb + 4];
            const float m0 = Pm[rb + 1], m1 = Pm[rb + 2], m2 = Pm[rb + 3];
            const float p0 = Pp[rb + 1], p1 = Pp[rb + 2], p2 = Pp[rb + 3];
            const float u0 = P0[rb + PW + 1], u1 = P0[rb + PW + 2], u2 = P0[rb + PW + 3];
            const float e0 = P0[rb - PW + 1], e1 = P0[rb - PW + 2], e2 = P0[rb - PW + 3];
            float d;
            d = p0 - a1; c0 = d * d * wl;
            d = m0 - a1; c1 = d * d * wl;
            d = u0 - a1; c2 = d * d * wl;
            d = e0 - a1; c3 = d * d * wl;
            d = a2 - a1; c4 = d * d * wl;
            d = a0 - a1; c5 = d * d * wl;
            d = p1 - a2; c0 = fmaf(d, d, c0);
            d = m1 - a2; c1 = fmaf(d, d, c1);
            d = u1 - a2; c2 = fmaf(d, d, c2);
            d = e1 - a2; c3 = fmaf(d, d, c3);
            d = a3 - a2; c4 = fmaf(d, d, c4);
            d = a1 - a2; c5 = fmaf(d, d, c5);
            d = p2 - a3; c0 = fmaf(d * d, wr, c0);
            d = m2 - a3; c1 = fmaf(d * d, wr, c1);
            d = u2 - a3; c2 = fmaf(d * d, wr, c2);
            d = e2 - a3; c3 = fmaf(d * d, wr, c3);
            d = a4 - a3; c4 = fmaf(d * d, wr, c4);
            d = a2 - a3; c5 = fmaf(d * d, wr, c5);
        }
        s_cx[0][cy][lx] = c0; s_cx[1][cy][lx] = c1; s_cx[2][cy][lx] = c2;
        s_cx[3][cy][lx] = c3; s_cx[4][cy][lx] = c4; s_cx[5][cy][lx] = c5;
    };

    // preload planes z0-2, z0-1 straight into smem; prefetch z0 into regs
    {
        float a1, a2;
        prefetch(z0 - 2, a1, a2); commit(s_img[0], a1, a2);
        prefetch(z0 - 1, a1, a2); commit(s_img[1], a1, a2);
    }
    float pv1, pv2;
    prefetch(z0, pv1, pv2);

    float S0[6], S1[6], S2[6];
#pragma unroll
    for (int c = 0; c < 6; c++) { S0[c] = 0.f; S1[c] = 0.f; S2[c] = 0.f; }

    float* r0 = s_img[0];
    float* r1 = s_img[1];
    float* r2 = s_img[2];

#pragma unroll 3
    for (int t = 0; t <= ZCHUNK + 1; ++t) {
        const int zs = z0 - 1 + t;                   // plane whose 2D-smoothed diff2 we build

        commit(r2, pv1, pv2);                        // plane zs+1 -> smem (cheap STS)
        prefetch(zs + 2, pv1, pv2);                  // kick off next plane's LDG now
        __syncthreads();                             // img plane ready

        const int zvalid = (unsigned)zs < (unsigned)N;
        if (zvalid) {
            stage2(r0, r1, r2, rbA, cyA, yvA);
            if (hasB) stage2(r0, r1, r2, rbB, cyB, yvB);
        }
        __syncthreads();                             // s_cx ready

#pragma unroll
        for (int c = 0; c < 6; c++) { S0[c] = S1[c]; S1[c] = S2[c]; }
        if (zvalid) {
#pragma unroll
            for (int c = 0; c < 6; c++)
                S2[c] = fmaf(A, s_cx[c][ly][lx] + s_cx[c][ly + 2][lx], s_cx[c][ly + 1][lx]);
        } else {
#pragma unroll
            for (int c = 0; c < 6; c++) S2[c] = 0.f;
        }

        if (t >= 2) {
            const int zo = zs - 1;
            float Dp[6];
            float sd = 0.f;
#pragma unroll
            for (int c = 0; c < 6; c++) {
                Dp[c] = NORM * fmaf(A, S0[c] + S2[c], S1[c]);
                sd += Dp[c];
            }
            const float inv = __fdividef(6.f, fmaf(6.f, EPS, sd));  // 1/(sd/6 + EPS)
            float num[6];
            float s = 0.f;
#pragma unroll
            for (int c = 0; c < 6; c++) { num[c] = __expf(-Dp[c] * inv); s += num[c]; }
            const float invs = __fdividef(1.f, s + EPS);
            const size_t base = ((size_t)zo * N + (by0 + ly)) * N + gx;
#pragma unroll
            for (int c = 0; c < 6; c++)
                outb[(size_t)c * VOL + base] = num[c] * invs;
        }

        float* tmp = r0; r0 = r1; r1 = r2; r2 = tmp;  // ring rotate (renamed under unroll)
    }
}

extern "C" void kernel_launch(void* const* d_in, const int* in_sizes, int n_in,
                              void* d_out, int out_size) {
    const float* img = (const float*)d_in[0];
    float* out = (float*)d_out;
    const int B = in_sizes[0] / (int)(N * N * N);
    dim3 block(TX, TY, 1);
    dim3 grid(N / TX, N / TY, B * NCHUNK);
    mind_kernel<<<grid, block>>>(img, out);
}

// round 4
// speedup vs baseline: 1.5171x; 1.0395x over previous
#include <cuda_runtime.h>

#define N 192
#define TX 32
#define TY 8
#define NT 256
#define ZCHUNK 96
#define NCHUNK 2          // N / ZCHUNK, compile-time
#define PW 36             // TX + 4
#define PH 12             // TY + 4
#define PLANE (PH*PW)     // 432
#define VOL ((size_t)N*(size_t)N*(size_t)N)

__global__ void __launch_bounds__(NT, 4)
mind_kernel(const float* __restrict__ img, float* __restrict__ out) {
    __shared__ float  s_img[3][PLANE];
    __shared__ float2 s_cx2[3][TY + 2][TX];   // channel pairs (0,1),(2,3),(4,5)

    const int lx  = threadIdx.x;
    const int ly  = threadIdx.y;
    const int tid = ly * TX + lx;
    const int bx0 = blockIdx.x * TX;
    const int by0 = blockIdx.y * TY;
    const int b   = blockIdx.z >> 1;                 // NCHUNK == 2
    const int z0  = (blockIdx.z & (NCHUNK - 1)) * ZCHUNK;

    constexpr float A    = 0.018315639f;             // exp(-4): 1D Gaussian side tap
    constexpr float NORM = 1.0f / ((1.f + 2.f * A) * (1.f + 2.f * A) * (1.f + 2.f * A));
    constexpr float EPS  = 1e-8f;

    const float* imgb = img + (size_t)b * VOL;
    float* outb = out + (size_t)b * 6 * VOL;

    // ---- hoisted halo-load geometry (iteration-invariant) ----
    int h1_off, h1_ok;
    {
        const int px = tid % PW, py = tid / PW;
        const int gxh = bx0 + px - 2, gyh = by0 + py - 2;
        h1_ok  = ((unsigned)gxh < (unsigned)N) & ((unsigned)gyh < (unsigned)N);
        h1_off = gyh * N + gxh;
    }
    int h2_off = 0, h2_ok = 0;
    const bool has2 = (tid < PLANE - NT);
    {
        const int i = tid + NT;
        if (i < PLANE) {
            const int px = i % PW, py = i / PW;
            const int gxh = bx0 + px - 2, gyh = by0 + py - 2;
            h2_ok  = ((unsigned)gxh < (unsigned)N) & ((unsigned)gyh < (unsigned)N);
            h2_off = gyh * N + gxh;
        }
    }

    // issue global loads for plane zp into registers (latency overlapped by caller)
    auto prefetch = [&](int zp, float& v1, float& v2) {
        const int zok = (unsigned)zp < (unsigned)N;
        const float* src = imgb + (size_t)zp * (N * N);
        v1 = 0.f; v2 = 0.f;
        if (zok & h1_ok) v1 = __ldg(src + h1_off);
        if (has2 && (zok & h2_ok)) v2 = __ldg(src + h2_off);
    };
    auto commit = [&](float* dst, float v1, float v2) {
        dst[tid] = v1;
        if (has2) dst[tid + NT] = v2;
    };

    // ---- hoisted stage-2 geometry ----
    const int   gx = bx0 + lx;
    const float wl = (gx >= 1)     ? A : 0.f;        // Gaussian x-tap masks at volume border
    const float wr = (gx <= N - 2) ? A : 0.f;

    const int  rbA = (ly + 1) * PW + lx;             // posA: y' = ly-1
    const int  cyA = ly;
    const int  yvA = (by0 + ly - 1) >= 0;
    const int  rbB = (9 + ly) * PW + lx;             // posB: y' = 7+ly (ly<2 only)
    const int  cyB = 8 + ly;
    const int  yvB = (by0 + 7 + ly) < N;
    const bool hasB = (ly < 2);

    auto stage2 = [&](const float* Pm, const float* P0, const float* Pp,
                      int rb, int cy, int yv) {
        float c0 = 0.f, c1 = 0.f, c2 = 0.f, c3 = 0.f, c4 = 0.f, c5 = 0.f;
        if (yv) {
            const float a0 = P0[rb],     a1 = P0[rb + 1], a2 = P0[rb + 2];
            const float a3 = P0[rb + 3], a4 = P0[rb + 4];
            const float m0 = Pm[rb + 1], m1 = Pm[rb + 2], m2 = Pm[rb + 3];
            const float p0 = Pp[rb + 1], p1 = Pp[rb + 2], p2 = Pp[rb + 3];
            const float u0 = P0[rb + PW + 1], u1 = P0[rb + PW + 2], u2 = P0[rb + PW + 3];
            const float e0 = P0[rb - PW + 1], e1 = P0[rb - PW + 2], e2 = P0[rb - PW + 3];
            float d;
            d = p0 - a1; c0 = d * d * wl;
            d = m0 - a1; c1 = d * d * wl;
            d = u0 - a1; c2 = d * d * wl;
            d = e0 - a1; c3 = d * d * wl;
            d = a2 - a1; c4 = d * d * wl;
            d = a0 - a1; c5 = d * d * wl;
            d = p1 - a2; c0 = fmaf(d, d, c0);
            d = m1 - a2; c1 = fmaf(d, d, c1);
            d = u1 - a2; c2 = fmaf(d, d, c2);
            d = e1 - a2; c3 = fmaf(d, d, c3);
            d = a3 - a2; c4 = fmaf(d, d, c4);
            d = a1 - a2; c5 = fmaf(d, d, c5);
            d = p2 - a3; c0 = fmaf(d * d, wr, c0);
            d = m2 - a3; c1 = fmaf(d * d, wr, c1);
            d = u2 - a3; c2 = fmaf(d * d, wr, c2);
            d = e2 - a3; c3 = fmaf(d * d, wr, c3);
            d = a4 - a3; c4 = fmaf(d * d, wr, c4);
            d = a2 - a3; c5 = fmaf(d * d, wr, c5);
        }
        s_cx2[0][cy][lx] = make_float2(c0, c1);
        s_cx2[1][cy][lx] = make_float2(c2, c3);
        s_cx2[2][cy][lx] = make_float2(c4, c5);
    };

    // preload planes z0-2, z0-1 straight into smem; prefetch z0 into regs
    {
        float a1, a2;
        prefetch(z0 - 2, a1, a2); commit(s_img[0], a1, a2);
        prefetch(z0 - 1, a1, a2); commit(s_img[1], a1, a2);
    }
    float pv1, pv2;
    prefetch(z0, pv1, pv2);

    float S0[6], S1[6], S2[6];
#pragma unroll
    for (int c = 0; c < 6; c++) { S0[c] = 0.f; S1[c] = 0.f; S2[c] = 0.f; }

    float* r0 = s_img[0];
    float* r1 = s_img[1];
    float* r2 = s_img[2];

#pragma unroll 3
    for (int t = 0; t <= ZCHUNK + 1; ++t) {
        const int zs = z0 - 1 + t;                   // plane whose 2D-smoothed diff2 we build

        commit(r2, pv1, pv2);                        // plane zs+1 -> smem (cheap STS)
        prefetch(zs + 2, pv1, pv2);                  // kick off next plane's LDG now
        __syncthreads();                             // img plane ready

        const int zvalid = (unsigned)zs < (unsigned)N;
        if (zvalid) {
            stage2(r0, r1, r2, rbA, cyA, yvA);
            if (hasB) stage2(r0, r1, r2, rbB, cyB, yvB);
        }
        __syncthreads();                             // s_cx ready

#pragma unroll
        for (int c = 0; c < 6; c++) { S0[c] = S1[c]; S1[c] = S2[c]; }
        if (zvalid) {
#pragma unroll
            for (int p = 0; p < 3; p++) {
                const float2 qm = s_cx2[p][ly][lx];
                const float2 qc = s_cx2[p][ly + 1][lx];
                const float2 qp = s_cx2[p][ly + 2][lx];
                S2[2 * p]     = fmaf(A, qm.x + qp.x, qc.x);
                S2[2 * p + 1] = fmaf(A, qm.y + qp.y, qc.y);
            }
        } else {
#pragma unroll
            for (int c = 0; c < 6; c++) S2[c] = 0.f;
        }

        if (t >= 2) {
            const int zo = zs - 1;
            float Dp[6];
            float sd = 0.f;
#pragma unroll
            for (int c = 0; c < 6; c++) {
                Dp[c] = NORM * fmaf(A, S0[c] + S2[c], S1[c]);
                sd += Dp[c];
            }
            const float inv = __fdividef(6.f, fmaf(6.f, EPS, sd));  // 1/(sd/6 + EPS)
            float num[6];
            float s = 0.f;
#pragma unroll
            for (int c = 0; c < 6; c++) { num[c] = __expf(-Dp[c] * inv); s += num[c]; }
            const float invs = __fdividef(1.f, s + EPS);
            const size_t base = ((size_t)zo * N + (by0 + ly)) * N + gx;
#pragma unroll
            for (int c = 0; c < 6; c++)
                outb[(size_t)c * VOL + base] = num[c] * invs;
        }

        float* tmp = r0; r0 = r1; r1 = r2; r2 = tmp;  // ring rotate (renamed under unroll)
    }
}

extern "C" void kernel_launch(void* const* d_in, const int* in_sizes, int n_in,
                              void* d_out, int out_size) {
    const float* img = (const float*)d_in[0];
    float* out = (float*)d_out;
    const int B = in_sizes[0] / (int)(N * N * N);
    dim3 block(TX, TY, 1);
    dim3 grid(N / TX, N / TY, B * NCHUNK);
    mind_kernel<<<grid, block>>>(img, out);
}

// round 5
// speedup vs baseline: 1.5181x; 1.0007x over previous
#include <cuda_runtime.h>

#define N 192
#define TX 32
#define TY 8
#define NT 256
#define ZCHUNK 96
#define NCHUNK 2          // N / ZCHUNK, compile-time
#define PW 36             // TX + 4
#define PH 12             // TY + 4
#define PLANE (PH*PW)     // 432
#define VOL ((size_t)N*(size_t)N*(size_t)N)

__global__ void __launch_bounds__(NT, 4)
mind_kernel(const float* __restrict__ img, float* __restrict__ out) {
    __shared__ float  s_img[3][PLANE];
    __shared__ float2 s_cx2[3][TY + 2][TX];   // channel pairs (0,1),(2,3),(4,5)

    const int lx  = threadIdx.x;
    const int ly  = threadIdx.y;
    const int tid = ly * TX + lx;
    const int bx0 = blockIdx.x * TX;
    const int by0 = blockIdx.y * TY;
    const int b   = blockIdx.z >> 1;                 // NCHUNK == 2
    const int z0  = (blockIdx.z & (NCHUNK - 1)) * ZCHUNK;

    constexpr float A    = 0.018315639f;             // exp(-4): 1D Gaussian side tap
    constexpr float NORM = 1.0f / ((1.f + 2.f * A) * (1.f + 2.f * A) * (1.f + 2.f * A));
    constexpr float EPS  = 1e-8f;

    const float* imgb = img + (size_t)b * VOL;
    float* outb = out + (size_t)b * 6 * VOL;

    // ---- hoisted halo-load geometry (iteration-invariant) ----
    int h1_off, h1_ok;
    {
        const int px = tid % PW, py = tid / PW;
        const int gxh = bx0 + px - 2, gyh = by0 + py - 2;
        h1_ok  = ((unsigned)gxh < (unsigned)N) & ((unsigned)gyh < (unsigned)N);
        h1_off = gyh * N + gxh;
    }
    int h2_off = 0, h2_ok = 0;
    const bool has2 = (tid < PLANE - NT);
    {
        const int i = tid + NT;
        if (i < PLANE) {
            const int px = i % PW, py = i / PW;
            const int gxh = bx0 + px - 2, gyh = by0 + py - 2;
            h2_ok  = ((unsigned)gxh < (unsigned)N) & ((unsigned)gyh < (unsigned)N);
            h2_off = gyh * N + gxh;
        }
    }

    // issue global loads for plane zp into registers (latency overlapped by caller)
    auto prefetch = [&](int zp, float& v1, float& v2) {
        const int zok = (unsigned)zp < (unsigned)N;
        const float* src = imgb + (size_t)zp * (N * N);
        v1 = 0.f; v2 = 0.f;
        if (zok & h1_ok) v1 = __ldg(src + h1_off);
        if (has2 && (zok & h2_ok)) v2 = __ldg(src + h2_off);
    };
    auto commit = [&](float* dst, float v1, float v2) {
        dst[tid] = v1;
        if (has2) dst[tid + NT] = v2;
    };

    // ---- hoisted stage-2 geometry ----
    const int   gx = bx0 + lx;
    const float wl = (gx >= 1)     ? A : 0.f;        // Gaussian x-tap masks at volume border
    const float wr = (gx <= N - 2) ? A : 0.f;

    const int  rbA = (ly + 1) * PW + lx;             // posA: y' = ly-1
    const int  cyA = ly;
    const int  yvA = (by0 + ly - 1) >= 0;
    const int  rbB = (9 + ly) * PW + lx;             // posB: y' = 7+ly (ly<2 only)
    const int  cyB = 8 + ly;
    const int  yvB = (by0 + 7 + ly) < N;
    const bool hasB = (ly < 2);

    auto stage2 = [&](const float* Pm, const float* P0, const float* Pp,
                      int rb, int cy, int yv) {
        float c0 = 0.f, c1 = 0.f, c2 = 0.f, c3 = 0.f, c4 = 0.f, c5 = 0.f;
        if (yv) {
            const float a0 = P0[rb],     a1 = P0[rb + 1], a2 = P0[rb + 2];
            const float a3 = P0[rb + 3], a4 = P0[rb + 4];
            const float m0 = Pm[rb + 1], m1 = Pm[rb + 2], m2 = Pm[rb + 3];
            const float p0 = Pp[rb + 1], p1 = Pp[rb + 2], p2 = Pp[rb + 3];
            const float u0 = P0[rb + PW + 1], u1 = P0[rb + PW + 2], u2 = P0[rb + PW + 3];
            const float e0 = P0[rb - PW + 1], e1 = P0[rb - PW + 2], e2 = P0[rb - PW + 3];
            float d;
            d = p0 - a1; c0 = d * d * wl;
            d = m0 - a1; c1 = d * d * wl;
            d = u0 - a1; c2 = d * d * wl;
            d = e0 - a1; c3 = d * d * wl;
            d = a2 - a1; c4 = d * d * wl;
            d = a0 - a1; c5 = d * d * wl;
            d = p1 - a2; c0 = fmaf(d, d, c0);
            d = m1 - a2; c1 = fmaf(d, d, c1);
            d = u1 - a2; c2 = fmaf(d, d, c2);
            d = e1 - a2; c3 = fmaf(d, d, c3);
            d = a3 - a2; c4 = fmaf(d, d, c4);
            d = a1 - a2; c5 = fmaf(d, d, c5);
            d = p2 - a3; c0 = fmaf(d * d, wr, c0);
            d = m2 - a3; c1 = fmaf(d * d, wr, c1);
            d = u2 - a3; c2 = fmaf(d * d, wr, c2);
            d = e2 - a3; c3 = fmaf(d * d, wr, c3);
            d = a4 - a3; c4 = fmaf(d * d, wr, c4);
            d = a2 - a3; c5 = fmaf(d * d, wr, c5);
        }
        s_cx2[0][cy][lx] = make_float2(c0, c1);
        s_cx2[1][cy][lx] = make_float2(c2, c3);
        s_cx2[2][cy][lx] = make_float2(c4, c5);
    };

    // preload planes z0-2, z0-1 straight into smem; prefetch z0 into regs
    {
        float a1, a2;
        prefetch(z0 - 2, a1, a2); commit(s_img[0], a1, a2);
        prefetch(z0 - 1, a1, a2); commit(s_img[1], a1, a2);
    }
    float pv1, pv2;
    prefetch(z0, pv1, pv2);

    float S0[6], S1[6], S2[6];
#pragma unroll
    for (int c = 0; c < 6; c++) { S0[c] = 0.f; S1[c] = 0.f; S2[c] = 0.f; }

    float* r0 = s_img[0];
    float* r1 = s_img[1];
    float* r2 = s_img[2];

#pragma unroll 3
    for (int t = 0; t <= ZCHUNK + 1; ++t) {
        const int zs = z0 - 1 + t;                   // plane whose 2D-smoothed diff2 we build

        commit(r2, pv1, pv2);                        // plane zs+1 -> smem (cheap STS)
        prefetch(zs + 2, pv1, pv2);                  // kick off next plane's LDG now
        __syncthreads();                             // img plane ready

        const int zvalid = (unsigned)zs < (unsigned)N;
        if (zvalid) {
            stage2(r0, r1, r2, rbA, cyA, yvA);
            if (hasB) stage2(r0, r1, r2, rbB, cyB, yvB);
        }
        __syncthreads();                             // s_cx ready

#pragma unroll
        for (int c = 0; c < 6; c++) { S0[c] = S1[c]; S1[c] = S2[c]; }
        if (zvalid) {
#pragma unroll
            for (int p = 0; p < 3; p++) {
                const float2 qm = s_cx2[p][ly][lx];
                const float2 qc = s_cx2[p][ly + 1][lx];
                const float2 qp = s_cx2[p][ly + 2][lx];
                S2[2 * p]     = fmaf(A, qm.x + qp.x, qc.x);
                S2[2 * p + 1] = fmaf(A, qm.y + qp.y, qc.y);
            }
        } else {
#pragma unroll
            for (int c = 0; c < 6; c++) S2[c] = 0.f;
        }

        if (t >= 2) {
            const int zo = zs - 1;
            float Dp[6];
            float sd = 0.f;
#pragma unroll
            for (int c = 0; c < 6; c++) {
                Dp[c] = NORM * fmaf(A, S0[c] + S2[c], S1[c]);
                sd += Dp[c];
            }
            const float inv = __fdividef(6.f, fmaf(6.f, EPS, sd));  // 1/(sd/6 + EPS)
            float num[6];
            float s = 0.f;
#pragma unroll
            for (int c = 0; c < 6; c++) { num[c] = __expf(-Dp[c] * inv); s += num[c]; }
            const float invs = __fdividef(1.f, s + EPS);
            const size_t base = ((size_t)zo * N + (by0 + ly)) * N + gx;
#pragma unroll
            for (int c = 0; c < 6; c++)
                outb[(size_t)c * VOL + base] = num[c] * invs;
        }

        float* tmp = r0; r0 = r1; r1 = r2; r2 = tmp;  // ring rotate (renamed under unroll)
    }
}

extern "C" void kernel_launch(void* const* d_in, const int* in_sizes, int n_in,
                              void* d_out, int out_size) {
    const float* img = (const float*)d_in[0];
    float* out = (float*)d_out;
    const int B = in_sizes[0] / (int)(N * N * N);
    dim3 block(TX, TY, 1);
    dim3 grid(N / TX, N / TY, B * NCHUNK);
    mind_kernel<<<grid, block>>>(img, out);
}

// round 6
// speedup vs baseline: 1.7129x; 1.1283x over previous
#include <cuda_runtime.h>

#define N 192
#define TX 32
#define TY 8
#define NT 256
#define ZCHUNK 96
#define NCHUNK 2
#define PW 36             // TX + 4
#define PH 12             // TY + 4
#define PLANE (PH*PW)     // 432
#define VOL ((size_t)N*(size_t)N*(size_t)N)

__global__ void __launch_bounds__(NT, 4)
mind_kernel(const float* __restrict__ img, float* __restrict__ out) {
    __shared__ float  s_img[2][PLANE];
    __shared__ float4 s_cx[11][TX];   // tile rows -2..8 of (c+z, c+y, c+x, c-x)

    const int lx  = threadIdx.x;
    const int ly  = threadIdx.y;
    const int tid = ly * TX + lx;
    const int bx0 = blockIdx.x * TX;
    const int by0 = blockIdx.y * TY;
    const int b   = blockIdx.z >> 1;                 // NCHUNK == 2
    const int z0  = (blockIdx.z & 1) * ZCHUNK;

    constexpr float A   = 0.018315639f;              // exp(-4): 1D Gaussian side tap
    constexpr float C6  = 6.683808e-08f;             // 6*EPS*(1+2A)^3  (NORM folded)
    constexpr float EPS = 1e-8f;

    const float* imgb = img + (size_t)b * VOL;
    float* outb = out + (size_t)b * 6 * VOL;

    // ---- hoisted halo-load geometry ----
    int h1_off, h1_ok;
    {
        const int px = tid % PW, py = tid / PW;
        const int gxh = bx0 + px - 2, gyh = by0 + py - 2;
        h1_ok  = ((unsigned)gxh < (unsigned)N) & ((unsigned)gyh < (unsigned)N);
        h1_off = gyh * N + gxh;
    }
    int h2_off = 0, h2_ok = 0;
    const bool has2 = (tid < PLANE - NT);
    {
        const int i = tid + NT;
        if (i < PLANE) {
            const int px = i % PW, py = i / PW;
            const int gxh = bx0 + px - 2, gyh = by0 + py - 2;
            h2_ok  = ((unsigned)gxh < (unsigned)N) & ((unsigned)gyh < (unsigned)N);
            h2_off = gyh * N + gxh;
        }
    }
    auto prefetch = [&](int zp, float& v1, float& v2) {
        const int zok = (unsigned)zp < (unsigned)N;
        const float* src = imgb + (size_t)zp * (N * N);
        v1 = 0.f; v2 = 0.f;
        if (zok & h1_ok) v1 = __ldg(src + h1_off);
        if (has2 && (zok & h2_ok)) v2 = __ldg(src + h2_off);
    };
    auto commit = [&](float* dst, float v1, float v2) {
        dst[tid] = v1;
        if (has2) dst[tid + NT] = v2;
    };

    // ---- hoisted per-thread geometry ----
    const int   gx  = bx0 + lx;
    const int   gy  = by0 + ly;
    const float wl  = (gx >= 1)     ? A : 0.f;   // x-conv border masks
    const float wr  = (gx <= N - 2) ? A : 0.f;
    const float wAy = (gy == N - 1) ? 0.f : A;   // -y: dropped tap at bottom edge

    const int  rbA  = ly * PW + lx;              // posA: tile row ly-2
    const int  idxA = ly;
    const int  rbB  = (8 + ly) * PW + lx;        // posB: tile row 6+ly (ly<3)
    const int  idxB = 8 + ly;
    const bool hasB = (ly < 3);

    // stage2: 4 x-convolved fields at one row; zero halo realizes all borders
    auto stage2 = [&](const float* P0, const float* Pp, int rb, int idx) {
        const float a0 = P0[rb],     a1 = P0[rb + 1], a2 = P0[rb + 2];
        const float a3 = P0[rb + 3], a4 = P0[rb + 4];
        const float u0 = P0[rb + PW + 1], u1 = P0[rb + PW + 2], u2 = P0[rb + PW + 3];
        const float p0 = Pp[rb + 1], p1 = Pp[rb + 2], p2 = Pp[rb + 3];
        const float q0 = a1 - a0, q1 = a2 - a1, q2 = a3 - a2, q3 = a4 - a3;
        const float s0 = q0 * q0, s1 = q1 * q1, s2 = q2 * q2, s3 = q3 * q3;
        const float cxp = fmaf(wr, s3, fmaf(wl, s1, s2));   // +x
        const float cxm = fmaf(wr, s2, fmaf(wl, s0, s1));   // -x
        const float d0 = u0 - a1, d1 = u1 - a2, d2 = u2 - a3;
        const float cyp = fmaf(wr, d2 * d2, fmaf(wl, d0 * d0, d1 * d1));   // +y
        const float e0 = p0 - a1, e1 = p1 - a2, e2 = p2 - a3;
        const float czp = fmaf(wr, e2 * e2, fmaf(wl, e0 * e0, e1 * e1));   // +z
        s_cx[idx][lx] = make_float4(czp, cyp, cxp, cxm);
    };

    // preload: plane z0-2 into rc; prefetch z0-1
    float* rc = s_img[0];
    float* rn = s_img[1];
    {
        float a1v, a2v;
        prefetch(z0 - 2, a1v, a2v); commit(rc, a1v, a2v);
    }
    float pv1, pv2;
    prefetch(z0 - 1, pv1, pv2);

    // register rings of xy-convolved fields T(zs)
    float Tza = 0.f, Tzb = 0.f, Tzc = 0.f, Tzd = 0.f;       // +z, 4 deep (serves -z)
    float Typa = 0.f, Typb = 0.f, Typc = 0.f;               // +y
    float Tyma = 0.f, Tymb = 0.f, Tymc = 0.f;               // -y
    float Txpa = 0.f, Txpb = 0.f, Txpc = 0.f;               // +x
    float Txma = 0.f, Txmb = 0.f, Txmc = 0.f;               // -x

#pragma unroll 2
    for (int t = 0; t <= ZCHUNK + 2; ++t) {
        const int zs = z0 - 2 + t;                   // plane whose T we compute

        commit(rn, pv1, pv2);                        // plane zs+1 -> smem
        prefetch(zs + 2, pv1, pv2);                  // next plane's LDG in flight
        __syncthreads();                             // planes zs, zs+1 ready

        stage2(rc, rn, rbA, idxA);
        if (hasB) stage2(rc, rn, rbB, idxB);
        __syncthreads();                             // s_cx ready; rc reads fenced

        // stage3: y-conv from exchange rows ly..ly+3 (tile rows ly-2..ly+1)
        const float4 r0 = s_cx[ly][lx];
        const float4 r1 = s_cx[ly + 1][lx];
        const float4 r2 = s_cx[ly + 2][lx];
        const float4 r3 = s_cx[ly + 3][lx];

        // shift rings
        Tza = Tzb; Tzb = Tzc; Tzc = Tzd;
        Typa = Typb; Typb = Typc;
        Tyma = Tymb; Tymb = Tymc;
        Txpa = Txpb; Txpb = Txpc;
        Txma = Txmb; Txmb = Txmc;

        Tzd  = fmaf(A, r1.x + r3.x, r2.x);                     // +z at zs
        Typc = fmaf(A, r1.y + r3.y, r2.y);                     // +y
        Tymc = fmaf(wAy, r2.y, fmaf(A, r0.y, r1.y));           // -y (delayed taps)
        Txpc = fmaf(A, r1.z + r3.z, r2.z);                     // +x
        Txmc = fmaf(A, r1.w + r3.w, r2.w);                     // -x

        if (t >= 3) {
            const int zo = zs - 1;
            const float wAz = (zo == N - 1) ? 0.f : A;         // -z dropped tap at far face
            float Dp[6];
            Dp[0] = fmaf(A, Tzb + Tzd, Tzc);                   // +z
            Dp[1] = fmaf(wAz, Tzc, fmaf(A, Tza, Tzb));         // -z (delayed taps)
            Dp[2] = fmaf(A, Typa + Typc, Typb);                // +y
            Dp[3] = fmaf(A, Tyma + Tymc, Tymb);                // -y
            Dp[4] = fmaf(A, Txpa + Txpc, Txpb);                // +x
            Dp[5] = fmaf(A, Txma + Txmc, Txmb);                // -x
            float sd = 0.f;
#pragma unroll
            for (int c = 0; c < 6; c++) sd += Dp[c];
            const float inv = __fdividef(6.f, sd + C6);        // 1/(mean*NORM + EPS), NORM folded
            float num[6];
            float s = 0.f;
#pragma unroll
            for (int c = 0; c < 6; c++) { num[c] = __expf(-Dp[c] * inv); s += num[c]; }
            const float invs = __fdividef(1.f, s + EPS);
            const size_t base = ((size_t)zo * N + gy) * N + gx;
#pragma unroll
            for (int c = 0; c < 6; c++)
                outb[(size_t)c * VOL + base] = num[c] * invs;
        }

        float* tmp = rc; rc = rn; rn = tmp;          // 2-plane ring swap
    }
}

extern "C" void kernel_launch(void* const* d_in, const int* in_sizes, int n_in,
                              void* d_out, int out_size) {
    const float* img = (const float*)d_in[0];
    float* out = (float*)d_out;
    const int B = in_sizes[0] / (int)(N * N * N);
    dim3 block(TX, TY, 1);
    dim3 grid(N / TX, N / TY, B * NCHUNK);
    mind_kernel<<<grid, block>>>(img, out);
}